// round 13
// baseline (speedup 1.0000x reference)
#include <cuda_runtime.h>
#include <cuda_fp16.h>
#include <cuda_bf16.h>
#include <cstdint>

// ---------------- problem constants ----------------
#define NS 2
#define CD 256
#define PD 4096            // 64*64
#define EPSF 1e-5f
#define LOG2E 1.4426950408889634f

// ---------------- device scratch (no runtime allocs allowed) ----------------
static __device__ uint8_t  g_dot8[(size_t)NS * PD * PD];  // 32 MiB: dot[n][pt][pi] in e4m3
static __device__ uint8_t  g_Tn[(size_t)NS * PD * CD];    // normalized T, fp8 e4m3 x16, [n][p][c]
static __device__ uint8_t  g_In[(size_t)NS * PD * CD];    // normalized I, fp8 e4m3 x16, [n][p][c]
static __device__ float g_meanT[CD];
static __device__ float g_colmin[NS * PD];   // min over pt of raw=(1-dot)/2 per (n,pi); >=0
static __device__ float g_S[NS * PD];        // sum_pt exp(c1*(dot-dmax)) per (n,pi)
static __device__ float g_diag[NS * PD];     // fp32 dot diagonal (exact numerator)
#define SC_CHUNKS 128
static __device__ float g_Sp[(size_t)SC_CHUNKS * NS * PD];  // 4 MiB partial column sums

// ---------------- asm helpers (baseline sm_80/sm_89 ISA only) ----------------
__device__ __forceinline__ uint32_t smem_to_u32(const void* p) {
    uint32_t a;
    asm("{ .reg .u64 t; cvta.to.shared.u64 t, %1; cvt.u32.u64 %0, t; }" : "=r"(a) : "l"(p));
    return a;
}
#define CP_ASYNC16(dst, src) \
    asm volatile("cp.async.cg.shared.global [%0], [%1], 16;" :: "r"(dst), "l"(src) : "memory")
#define CP_COMMIT() asm volatile("cp.async.commit_group;" ::: "memory")
#define CP_WAIT(N)  asm volatile("cp.async.wait_group %0;" :: "n"(N) : "memory")
#define NAMED_BAR64(id) asm volatile("bar.sync %0, 64;" :: "r"(id) : "memory")

#define LDSM_X4(R, addr) \
    asm volatile("ldmatrix.sync.aligned.m8n8.x4.shared.b16 {%0,%1,%2,%3}, [%4];" \
        : "=r"((R)[0]), "=r"((R)[1]), "=r"((R)[2]), "=r"((R)[3]) : "r"(addr))

// fp8 e4m3 MMA: m16n8k32, A row-major (K-major), B col-major (K-major), f32 accum
#define MMA_FP8(D, A, B0, B1) \
    asm volatile("mma.sync.aligned.m16n8k32.row.col.f32.e4m3.e4m3.f32 " \
        "{%0,%1,%2,%3}, {%4,%5,%6,%7}, {%8,%9}, {%0,%1,%2,%3};" \
        : "+f"((D)[0]), "+f"((D)[1]), "+f"((D)[2]), "+f"((D)[3]) \
        : "r"((A)[0]), "r"((A)[1]), "r"((A)[2]), "r"((A)[3]), "r"(B0), "r"(B1))

// pack two floats -> e4m3x2 (lo = first elem, hi = second elem)
__device__ __forceinline__ uint16_t pack_e4m3(float lo, float hi) {
    uint16_t r;
    asm("cvt.rn.satfinite.e4m3x2.f32 %0, %1, %2;" : "=h"(r) : "f"(hi), "f"(lo));
    return r;
}
// unpack e4m3x2 (16 bits) -> half2
__device__ __forceinline__ __half2 unpack_e4m3(uint16_t v) {
    uint32_t r;
    asm("cvt.rn.f16x2.e4m3x2 %0, %1;" : "=r"(r) : "h"(v));
    return *(__half2*)&r;
}
__device__ __forceinline__ float ex2(float x) {
    float r;
    asm("ex2.approx.ftz.f32 %0, %1;" : "=f"(r) : "f"(x));
    return r;
}
__device__ __forceinline__ float fexp(float x) {
    return ex2(fmaxf(x, -120.0f) * LOG2E);
}

// ---------------- kernel 1: meanT per channel (+ fused colmin init) ----------------
__global__ void k_mean(const float* __restrict__ T) {
    int c = blockIdx.x;       // 256
    int tid = threadIdx.x;    // 256
    if (tid < 32) {           // 256 blocks x 32 = 8192 = NS*PD
        g_colmin[c * 32 + tid] = 3.402823466e38f;
    }
    float s = 0.0f;
    #pragma unroll
    for (int n = 0; n < NS; n++) {
        const float4* b4 = (const float4*)(T + ((size_t)n * CD + c) * PD);
        #pragma unroll
        for (int i = tid; i < PD / 4; i += 256) {
            float4 v = b4[i];
            s += v.x + v.y + v.z + v.w;
        }
    }
    __shared__ float sh[256];
    sh[tid] = s; __syncthreads();
    for (int o = 128; o > 0; o >>= 1) { if (tid < o) sh[tid] += sh[tid + o]; __syncthreads(); }
    if (tid == 0) g_meanT[c] = sh[0] * (1.0f / (float)(NS * PD));
}

// ---------------- kernel 2: center + normalize(+x16) + transpose -> fp8 ----------------
#define NP 32
__global__ void __launch_bounds__(256) k_norm2(const float* __restrict__ I,
                                               const float* __restrict__ T) {
    const float* X = blockIdx.z ? I : T;
    uint8_t* out = blockIdx.z ? g_In : g_Tn;
    int n = blockIdx.y;
    int p0 = blockIdx.x * NP;
    int tid = threadIdx.x;
    __shared__ float buf[CD][NP + 1];   // [c][p]
    __shared__ float nrm[8][NP];
    __shared__ float scl[NP];

    const float* base = X + (size_t)n * CD * PD + p0;
    #pragma unroll
    for (int it = 0; it < 8; it++) {
        int idx = it * 256 + tid;       // 2048 = 256 c * 8 float4
        int c = idx >> 3, j = idx & 7;
        float4 v = *(const float4*)(base + (size_t)c * PD + j * 4);
        float mc = g_meanT[c];
        buf[c][j * 4 + 0] = v.x - mc;
        buf[c][j * 4 + 1] = v.y - mc;
        buf[c][j * 4 + 2] = v.z - mc;
        buf[c][j * 4 + 3] = v.w - mc;
    }
    __syncthreads();
    {
        int p = tid & 31, k = tid >> 5;   // warp k sums c-chunk k*32..k*32+31
        float s = 0.0f;
        #pragma unroll
        for (int m = 0; m < 32; m++) { float v = buf[k * 32 + m][p]; s += v * v; }
        nrm[k][p] = s;
    }
    __syncthreads();
    if (tid < NP) {
        float t = 0.0f;
        #pragma unroll
        for (int k = 0; k < 8; k++) t += nrm[k][tid];
        scl[tid] = rsqrtf(t) * 16.0f;   // x16 scale: e4m3 values ~O(1)
    }
    __syncthreads();
    uint8_t* ob = out + ((size_t)n * PD + p0) * CD;
    #pragma unroll
    for (int it = 0; it < 4; it++) {
        int idx = it * 256 + tid;       // 1024 = 32 p * 32 8-byte groups
        int p = idx >> 5, q = idx & 31;
        float sc = scl[p];
        uint16_t h[4];
        #pragma unroll
        for (int i = 0; i < 4; i++) {
            float a = buf[q * 8 + 2 * i + 0][p] * sc;
            float b = buf[q * 8 + 2 * i + 1][p] * sc;
            h[i] = pack_e4m3(a, b);
        }
        uint2 u;
        u.x = (uint32_t)h[0] | ((uint32_t)h[1] << 16);
        u.y = (uint32_t)h[2] | ((uint32_t)h[3] << 16);
        *(uint2*)(ob + (size_t)p * CD + q * 8) = u;
    }
}

// ---------------- kernel 3: persistent fp8 MMA GEMM, 128x128 tiles, 2 CTAs/SM ----------------
#define BM 128
#define BN 128
#define PITCH 144                 // 128 fp8 bytes + 16B pad
#define ASZ (BM * PITCH)          // 18432
#define BSZ (BN * PITCH)          // 18432
#define STG (ASZ + BSZ)           // 36864
#define EPI_OFF (2 * STG)         // 73728
#define EPITCH8 144               // epilogue fp8 row pitch (128 + 16)
#define GEMM_SMEM_BYTES (EPI_OFF + BM * EPITCH8)  // 73728 + 18432 = 92160
#define GRID_GEMM 296             // 2 CTAs per SM
#define NTILES (NS * (PD / BM) * (PD / BN))       // 2048

__device__ __forceinline__ void gemm_load_stage(
    uint32_t sb, int stage, int kc, int tid,
    const uint8_t* Asrc, const uint8_t* Bsrc) {
    uint32_t base = sb + stage * STG;
    #pragma unroll
    for (int i = 0; i < 4; i++) {               // A: 128 rows x 8 chunks = 1024
        int id = tid + i * 256;
        int row = id >> 3, g = id & 7;
        CP_ASYNC16(base + row * PITCH + g * 16, Asrc + (size_t)row * CD + kc * 128 + g * 16);
    }
    #pragma unroll
    for (int i = 0; i < 4; i++) {               // B: 128 rows x 8 chunks = 1024
        int id = tid + i * 256;
        int row = id >> 3, g = id & 7;
        CP_ASYNC16(base + ASZ + row * PITCH + g * 16, Bsrc + (size_t)row * CD + kc * 128 + g * 16);
    }
}

__device__ __forceinline__ void gemm_compute_chunk(uint32_t aB, uint32_t bB, float d[2][8][4]) {
    #pragma unroll
    for (int kk = 0; kk < 4; kk++) {   // 4 x k32 (32 bytes each)
        uint32_t a[2][4], b[4][4];
        LDSM_X4(a[0], aB + kk * 32);
        LDSM_X4(a[1], aB + 16 * PITCH + kk * 32);
        #pragma unroll
        for (int nb = 0; nb < 4; nb++)
            LDSM_X4(b[nb], bB + nb * 16 * PITCH + kk * 32);
        #pragma unroll
        for (int mi = 0; mi < 2; mi++)
            #pragma unroll
            for (int ni = 0; ni < 8; ni++) {
                uint32_t* bp = b[ni >> 1];
                MMA_FP8(d[mi][ni], a[mi], bp[(ni & 1) * 2], bp[(ni & 1) * 2 + 1]);
            }
    }
}

__device__ __forceinline__ void gemm_decode(int t, const uint8_t** A, const uint8_t** B,
                                            int* n2, int* pt0, int* pi0) {
    *n2 = t >> 10;                // 1024 tiles per sample
    int rem = t & 1023;
    *pt0 = (rem >> 5) * BM;       // 32 pt tiles
    *pi0 = (rem & 31) * BN;       // 32 pi tiles
    *A = g_Tn + ((size_t)(*n2) * PD + *pt0) * CD;
    *B = g_In + ((size_t)(*n2) * PD + *pi0) * CD;
}

__global__ void __launch_bounds__(256, 2) k_gemm() {
    extern __shared__ char smem[];
    uint32_t sb = smem_to_u32(smem);
    int tid = threadIdx.x, lane = tid & 31, wid = tid >> 5;

    int mw = wid & 3;               // m-group: 2 warps (wid&3 equal) own rows m0..m0+31
    int m0 = mw * 32;
    int n0 = (wid >> 2) * 64;       // 2 N-warps x 64 cols
    uint32_t aOff = (uint32_t)((m0 + (lane & 15)) * PITCH + (lane >> 4) * 16);
    uint32_t bOff = (uint32_t)(ASZ + (n0 + (lane & 7) + ((lane >> 4) * 8)) * PITCH
                               + ((lane >> 3) & 1) * 16);
    int gID = lane >> 2, tig = lane & 3;
    int gtid = (wid >> 2) * 32 + lane;   // 0..63 within m-group
    const float RS = 1.0f / 256.0f;      // undo the x16*x16 feature scaling

    int t = blockIdx.x;
    if (t >= NTILES) return;
    const uint8_t *Asrc, *Bsrc;
    int n2, pt0, pi0;
    gemm_decode(t, &Asrc, &Bsrc, &n2, &pt0, &pi0);

    gemm_load_stage(sb, 0, 0, tid, Asrc, Bsrc); CP_COMMIT();
    gemm_load_stage(sb, 1, 1, tid, Asrc, Bsrc); CP_COMMIT();

    while (true) {
        int tn = t + GRID_GEMM;
        bool more = (tn < NTILES);
        const uint8_t *An = nullptr, *Bn = nullptr;
        int nn2, npt0, npi0;
        if (more) gemm_decode(tn, &An, &Bn, &nn2, &npt0, &npi0);

        float d[2][8][4] = {};

        CP_WAIT(1); __syncthreads();
        gemm_compute_chunk(sb + aOff, sb + bOff, d);
        __syncthreads();
        if (more) { gemm_load_stage(sb, 0, 0, tid, An, Bn); CP_COMMIT(); }

        CP_WAIT(1); __syncthreads();
        gemm_compute_chunk(sb + STG + aOff, sb + STG + bOff, d);
        __syncthreads();
        if (more) { gemm_load_stage(sb, 1, 1, tid, An, Bn); CP_COMMIT(); }

        // ---- fp32 diagonal sidecar (only the 32 diagonal tiles) ----
        if (pt0 == pi0) {
            #pragma unroll
            for (int ni = 0; ni < 8; ni++) {
                int col = n0 + ni * 8 + tig * 2;
                #pragma unroll
                for (int mi = 0; mi < 2; mi++) {
                    int row = m0 + mi * 16 + gID;
                    #pragma unroll
                    for (int k = 0; k < 4; k++) {
                        int r = row + (k >> 1) * 8, c = col + (k & 1);
                        if (r == c) g_diag[(size_t)n2 * PD + pt0 + r] = d[mi][ni][k] * RS;
                    }
                }
            }
        }

        // ---- epilogue: per-m-group (named barriers, 64 thr), fp8 staging ----
        char* epi = smem + EPI_OFF;
        NAMED_BAR64(1 + mw);   // group's previous-tile epi reads complete before overwrite
        #pragma unroll
        for (int ni = 0; ni < 8; ni++) {
            float mx0 = -2.0f, mx1 = -2.0f;
            int col = n0 + ni * 8 + tig * 2;
            #pragma unroll
            for (int mi = 0; mi < 2; mi++) {
                float* dd = d[mi][ni];
                float v0 = dd[0] * RS, v1 = dd[1] * RS;
                float v2 = dd[2] * RS, v3 = dd[3] * RS;
                int row = m0 + mi * 16 + gID;
                *(uint16_t*)(epi + row * EPITCH8 + col) = pack_e4m3(v0, v1);
                *(uint16_t*)(epi + (row + 8) * EPITCH8 + col) = pack_e4m3(v2, v3);
                mx0 = fmaxf(mx0, fmaxf(v0, v2));
                mx1 = fmaxf(mx1, fmaxf(v1, v3));
            }
            #pragma unroll
            for (int o = 4; o < 32; o <<= 1) {
                mx0 = fmaxf(mx0, __shfl_xor_sync(0xffffffffu, mx0, o));
                mx1 = fmaxf(mx1, __shfl_xor_sync(0xffffffffu, mx1, o));
            }
            if (lane < 4) {
                int pi = pi0 + col;
                atomicMin((int*)&g_colmin[(size_t)n2 * PD + pi],
                          __float_as_int(0.5f - 0.5f * mx0));
                atomicMin((int*)&g_colmin[(size_t)n2 * PD + pi + 1],
                          __float_as_int(0.5f - 0.5f * mx1));
            }
        }
        NAMED_BAR64(1 + mw);   // group's epi rows fully written
        #pragma unroll
        for (int it = 0; it < 4; it++) {
            int idx = it * 64 + gtid;          // 256 = 32 rows x 8 uint4
            int r = m0 + (idx >> 3), q = idx & 7;
            uint4 v = *(uint4*)(epi + r * EPITCH8 + q * 16);
            *(uint4*)(g_dot8 + ((size_t)n2 * PD + pt0 + r) * PD + pi0 + q * 16) = v;
        }

        if (!more) break;
        t = tn; Asrc = An; Bsrc = Bn; n2 = nn2; pt0 = npt0; pi0 = npi0;
    }
}

// ---------------- kernel 4: partial column sums (no atomics, two-stage) ----------------
// Each block sums SC_ROWS=32 rows of exp(c1*(dot-dmax)) for its 1024-column strip
// and writes UNCONTENDED partials to g_Sp[chunk][n][pi]. 1024 blocks -> high occ,
// zero atomic serialization. Reverse traversal keeps the GEMM's freshest L2 lines.
#define SC_ROWS 32
__global__ void __launch_bounds__(256) k_sumcols() {
    int n = (NS - 1) - (int)blockIdx.z;
    int chunk = blockIdx.y;
    int pi = (blockIdx.x * 256 + threadIdx.x) * 4;
    int pt0 = PD - SC_ROWS - chunk * SC_ROWS;
    float4 mn4 = *(float4*)&g_colmin[(size_t)n * PD + pi];
    float mns[4] = {mn4.x, mn4.y, mn4.z, mn4.w};
    float c2[4], bs[4], sum[4];
    #pragma unroll
    for (int j = 0; j < 4; j++) {
        c2[j] = (5.0f * LOG2E) / (mns[j] + EPSF);
        bs[j] = -c2[j] * (1.0f - 2.0f * mns[j]);   // -c2*dmax
        sum[j] = 0.0f;
    }
    const uint8_t* col = g_dot8 + ((size_t)n * PD + pt0) * PD + pi;
    #pragma unroll
    for (int r = 0; r < SC_ROWS; r++) {
        uint32_t v = *(const uint32_t*)(col + (size_t)r * PD);
        float2 f0 = __half22float2(unpack_e4m3((uint16_t)(v & 0xffff)));
        float2 f1 = __half22float2(unpack_e4m3((uint16_t)(v >> 16)));
        sum[0] += ex2(fmaf(f0.x, c2[0], bs[0]));
        sum[1] += ex2(fmaf(f0.y, c2[1], bs[1]));
        sum[2] += ex2(fmaf(f1.x, c2[2], bs[2]));
        sum[3] += ex2(fmaf(f1.y, c2[3], bs[3]));
    }
    *(float4*)&g_Sp[((size_t)chunk * NS + n) * PD + pi] = make_float4(sum[0], sum[1], sum[2], sum[3]);
}

// ---------------- kernel 4b: fold the 128 partials per column into g_S ----------------
__global__ void __launch_bounds__(256) k_reduceS() {
    int idx = blockIdx.x * 256 + threadIdx.x;   // 0..NS*PD-1; consecutive -> coalesced
    float s = 0.0f;
    #pragma unroll 8
    for (int c = 0; c < SC_CHUNKS; c++)
        s += g_Sp[(size_t)c * NS * PD + idx];
    g_S[idx] = s;
}

// ---------------- kernel 5: final scalar ----------------
// cx_sp is exactly the identity in fp32 (off-diagonal exponents <= -225 underflow),
// so m[pt] = 0.5 * (1 + cx_feat[pt][pt]); diagonal comes from the fp32 sidecar.
__global__ void k_final(float* __restrict__ out) {
    __shared__ float sh[256];
    __shared__ float lossn[NS];
    int tid = threadIdx.x;
    for (int n = 0; n < NS; n++) {
        float s = 0.0f;
        for (int p = tid; p < PD; p += 256) {
            float mn = g_colmin[(size_t)n * PD + p];
            float c1 = 5.0f / (mn + EPSF);
            float dmax = 1.0f - 2.0f * mn;
            float dd = g_diag[(size_t)n * PD + p];
            float cxf = fexp(c1 * (dd - dmax)) / g_S[(size_t)n * PD + p];
            s += 0.5f + 0.5f * cxf;
        }
        sh[tid] = s; __syncthreads();
        for (int o = 128; o > 0; o >>= 1) { if (tid < o) sh[tid] += sh[tid + o]; __syncthreads(); }
        if (tid == 0) lossn[n] = -logf(sh[0] * (1.0f / (float)PD));
        __syncthreads();
    }
    if (tid == 0) {
        float acc = 0.0f;
        for (int n = 0; n < NS; n++) acc += lossn[n];
        out[0] = acc * (1.0f / (float)NS);
    }
}

// ---------------- launch ----------------
extern "C" void kernel_launch(void* const* d_in, const int* in_sizes, int n_in,
                              void* d_out, int out_size) {
    const float* I = (const float*)d_in[0];
    const float* T = (const float*)d_in[1];
    float* out = (float*)d_out;

    cudaFuncSetAttribute(k_gemm, cudaFuncAttributeMaxDynamicSharedMemorySize, GEMM_SMEM_BYTES);

    k_mean<<<CD, 256>>>(T);
    k_norm2<<<dim3(PD / NP, NS, 2), 256>>>(I, T);
    k_gemm<<<GRID_GEMM, 256, GEMM_SMEM_BYTES>>>();
    k_sumcols<<<dim3(PD / 1024, SC_CHUNKS, NS), 256>>>();
    k_reduceS<<<NS * PD / 256, 256>>>();
    k_final<<<1, 256>>>(out);
}

// round 14
// speedup vs baseline: 1.0177x; 1.0177x over previous
#include <cuda_runtime.h>
#include <cuda_fp16.h>
#include <cuda_bf16.h>
#include <cstdint>

// ---------------- problem constants ----------------
#define NS 2
#define CD 256
#define PD 4096            // 64*64
#define EPSF 1e-5f
#define LOG2E 1.4426950408889634f

// ---------------- device scratch (no runtime allocs allowed) ----------------
static __device__ uint8_t  g_dot8[(size_t)NS * PD * PD];  // 32 MiB: dot[n][pt][pi] in e4m3
static __device__ uint8_t  g_Tn[(size_t)NS * PD * CD];    // normalized T, fp8 e4m3 x16, [n][p][c]
static __device__ uint8_t  g_In[(size_t)NS * PD * CD];    // normalized I, fp8 e4m3 x16, [n][p][c]
static __device__ float g_meanT[CD];
static __device__ float g_colmin[NS * PD];   // min over pt of raw=(1-dot)/2 per (n,pi); >=0
static __device__ float g_S[NS * PD];        // sum_pt exp(c1*(dot-dmax)) per (n,pi)
static __device__ float g_diag[NS * PD];     // fp32 dot diagonal (exact numerator)
#define SC_CHUNKS 128
static __device__ float g_Sp[(size_t)SC_CHUNKS * NS * PD];  // 4 MiB partial column sums

// ---------------- asm helpers (baseline sm_80/sm_89 ISA only) ----------------
__device__ __forceinline__ uint32_t smem_to_u32(const void* p) {
    uint32_t a;
    asm("{ .reg .u64 t; cvta.to.shared.u64 t, %1; cvt.u32.u64 %0, t; }" : "=r"(a) : "l"(p));
    return a;
}
#define CP_ASYNC16(dst, src) \
    asm volatile("cp.async.cg.shared.global [%0], [%1], 16;" :: "r"(dst), "l"(src) : "memory")
#define CP_COMMIT() asm volatile("cp.async.commit_group;" ::: "memory")
#define CP_WAIT(N)  asm volatile("cp.async.wait_group %0;" :: "n"(N) : "memory")
#define NAMED_BAR64(id) asm volatile("bar.sync %0, 64;" :: "r"(id) : "memory")

#define LDSM_X4(R, addr) \
    asm volatile("ldmatrix.sync.aligned.m8n8.x4.shared.b16 {%0,%1,%2,%3}, [%4];" \
        : "=r"((R)[0]), "=r"((R)[1]), "=r"((R)[2]), "=r"((R)[3]) : "r"(addr))

// fp8 e4m3 MMA: m16n8k32, A row-major (K-major), B col-major (K-major), f32 accum
#define MMA_FP8(D, A, B0, B1) \
    asm volatile("mma.sync.aligned.m16n8k32.row.col.f32.e4m3.e4m3.f32 " \
        "{%0,%1,%2,%3}, {%4,%5,%6,%7}, {%8,%9}, {%0,%1,%2,%3};" \
        : "+f"((D)[0]), "+f"((D)[1]), "+f"((D)[2]), "+f"((D)[3]) \
        : "r"((A)[0]), "r"((A)[1]), "r"((A)[2]), "r"((A)[3]), "r"(B0), "r"(B1))

// pack two floats -> e4m3x2 (lo = first elem, hi = second elem)
__device__ __forceinline__ uint16_t pack_e4m3(float lo, float hi) {
    uint16_t r;
    asm("cvt.rn.satfinite.e4m3x2.f32 %0, %1, %2;" : "=h"(r) : "f"(hi), "f"(lo));
    return r;
}
// unpack e4m3x2 (16 bits) -> half2
__device__ __forceinline__ __half2 unpack_e4m3(uint16_t v) {
    uint32_t r;
    asm("cvt.rn.f16x2.e4m3x2 %0, %1;" : "=r"(r) : "h"(v));
    return *(__half2*)&r;
}
__device__ __forceinline__ float ex2(float x) {
    float r;
    asm("ex2.approx.ftz.f32 %0, %1;" : "=f"(r) : "f"(x));
    return r;
}
__device__ __forceinline__ float fexp(float x) {
    return ex2(fmaxf(x, -120.0f) * LOG2E);
}

// ---------------- kernel 1: meanT per channel (+ fused accumulator init) ----------------
__global__ void k_mean(const float* __restrict__ T) {
    int c = blockIdx.x;       // 256
    int tid = threadIdx.x;    // 256
    if (tid < 32) {           // 256 blocks x 32 = 8192 = NS*PD
        int i = c * 32 + tid;
        g_colmin[i] = 3.402823466e38f;
        g_S[i] = 0.0f;
    }
    float s = 0.0f;
    #pragma unroll
    for (int n = 0; n < NS; n++) {
        const float4* b4 = (const float4*)(T + ((size_t)n * CD + c) * PD);
        #pragma unroll
        for (int i = tid; i < PD / 4; i += 256) {
            float4 v = b4[i];
            s += v.x + v.y + v.z + v.w;
        }
    }
    __shared__ float sh[256];
    sh[tid] = s; __syncthreads();
    for (int o = 128; o > 0; o >>= 1) { if (tid < o) sh[tid] += sh[tid + o]; __syncthreads(); }
    if (tid == 0) g_meanT[c] = sh[0] * (1.0f / (float)(NS * PD));
}

// ---------------- kernel 2: center + normalize(+x16) + transpose -> fp8 ----------------
#define NP 32
__global__ void __launch_bounds__(256) k_norm2(const float* __restrict__ I,
                                               const float* __restrict__ T) {
    const float* X = blockIdx.z ? I : T;
    uint8_t* out = blockIdx.z ? g_In : g_Tn;
    int n = blockIdx.y;
    int p0 = blockIdx.x * NP;
    int tid = threadIdx.x;
    __shared__ float buf[CD][NP + 1];   // [c][p]
    __shared__ float nrm[8][NP];
    __shared__ float scl[NP];

    const float* base = X + (size_t)n * CD * PD + p0;
    #pragma unroll
    for (int it = 0; it < 8; it++) {
        int idx = it * 256 + tid;       // 2048 = 256 c * 8 float4
        int c = idx >> 3, j = idx & 7;
        float4 v = *(const float4*)(base + (size_t)c * PD + j * 4);
        float mc = g_meanT[c];
        buf[c][j * 4 + 0] = v.x - mc;
        buf[c][j * 4 + 1] = v.y - mc;
        buf[c][j * 4 + 2] = v.z - mc;
        buf[c][j * 4 + 3] = v.w - mc;
    }
    __syncthreads();
    {
        int p = tid & 31, k = tid >> 5;   // warp k sums c-chunk k*32..k*32+31
        float s = 0.0f;
        #pragma unroll
        for (int m = 0; m < 32; m++) { float v = buf[k * 32 + m][p]; s += v * v; }
        nrm[k][p] = s;
    }
    __syncthreads();
    if (tid < NP) {
        float t = 0.0f;
        #pragma unroll
        for (int k = 0; k < 8; k++) t += nrm[k][tid];
        scl[tid] = rsqrtf(t) * 16.0f;   // x16 scale: e4m3 values ~O(1)
    }
    __syncthreads();
    uint8_t* ob = out + ((size_t)n * PD + p0) * CD;
    #pragma unroll
    for (int it = 0; it < 4; it++) {
        int idx = it * 256 + tid;       // 1024 = 32 p * 32 8-byte groups
        int p = idx >> 5, q = idx & 31;
        float sc = scl[p];
        uint16_t h[4];
        #pragma unroll
        for (int i = 0; i < 4; i++) {
            float a = buf[q * 8 + 2 * i + 0][p] * sc;
            float b = buf[q * 8 + 2 * i + 1][p] * sc;
            h[i] = pack_e4m3(a, b);
        }
        uint2 u;
        u.x = (uint32_t)h[0] | ((uint32_t)h[1] << 16);
        u.y = (uint32_t)h[2] | ((uint32_t)h[3] << 16);
        *(uint2*)(ob + (size_t)p * CD + q * 8) = u;
    }
}

// ---------------- kernel 3: persistent fp8 MMA GEMM, 128x128 tiles, 2 CTAs/SM ----------------
#define BM 128
#define BN 128
#define PITCH 144                 // 128 fp8 bytes + 16B pad
#define ASZ (BM * PITCH)          // 18432
#define BSZ (BN * PITCH)          // 18432
#define STG (ASZ + BSZ)           // 36864
#define EPI_OFF (2 * STG)         // 73728
#define EPITCH8 144               // epilogue fp8 row pitch (128 + 16)
#define GEMM_SMEM_BYTES (EPI_OFF + BM * EPITCH8)  // 73728 + 18432 = 92160
#define GRID_GEMM 296             // 2 CTAs per SM
#define NTILES (NS * (PD / BM) * (PD / BN))       // 2048

__device__ __forceinline__ void gemm_load_stage(
    uint32_t sb, int stage, int kc, int tid,
    const uint8_t* Asrc, const uint8_t* Bsrc) {
    uint32_t base = sb + stage * STG;
    #pragma unroll
    for (int i = 0; i < 4; i++) {               // A: 128 rows x 8 chunks = 1024
        int id = tid + i * 256;
        int row = id >> 3, g = id & 7;
        CP_ASYNC16(base + row * PITCH + g * 16, Asrc + (size_t)row * CD + kc * 128 + g * 16);
    }
    #pragma unroll
    for (int i = 0; i < 4; i++) {               // B: 128 rows x 8 chunks = 1024
        int id = tid + i * 256;
        int row = id >> 3, g = id & 7;
        CP_ASYNC16(base + ASZ + row * PITCH + g * 16, Bsrc + (size_t)row * CD + kc * 128 + g * 16);
    }
}

__device__ __forceinline__ void gemm_compute_chunk(uint32_t aB, uint32_t bB, float d[2][8][4]) {
    #pragma unroll
    for (int kk = 0; kk < 4; kk++) {   // 4 x k32 (32 bytes each)
        uint32_t a[2][4], b[4][4];
        LDSM_X4(a[0], aB + kk * 32);
        LDSM_X4(a[1], aB + 16 * PITCH + kk * 32);
        #pragma unroll
        for (int nb = 0; nb < 4; nb++)
            LDSM_X4(b[nb], bB + nb * 16 * PITCH + kk * 32);
        #pragma unroll
        for (int mi = 0; mi < 2; mi++)
            #pragma unroll
            for (int ni = 0; ni < 8; ni++) {
                uint32_t* bp = b[ni >> 1];
                MMA_FP8(d[mi][ni], a[mi], bp[(ni & 1) * 2], bp[(ni & 1) * 2 + 1]);
            }
    }
}

__device__ __forceinline__ void gemm_decode(int t, const uint8_t** A, const uint8_t** B,
                                            int* n2, int* pt0, int* pi0) {
    *n2 = t >> 10;                // 1024 tiles per sample
    int rem = t & 1023;
    *pt0 = (rem >> 5) * BM;       // 32 pt tiles
    *pi0 = (rem & 31) * BN;       // 32 pi tiles
    *A = g_Tn + ((size_t)(*n2) * PD + *pt0) * CD;
    *B = g_In + ((size_t)(*n2) * PD + *pi0) * CD;
}

__global__ void __launch_bounds__(256, 2) k_gemm() {
    extern __shared__ char smem[];
    uint32_t sb = smem_to_u32(smem);
    int tid = threadIdx.x, lane = tid & 31, wid = tid >> 5;

    int mw = wid & 3;               // m-group: 2 warps (wid&3 equal) own rows m0..m0+31
    int m0 = mw * 32;
    int n0 = (wid >> 2) * 64;       // 2 N-warps x 64 cols
    uint32_t aOff = (uint32_t)((m0 + (lane & 15)) * PITCH + (lane >> 4) * 16);
    uint32_t bOff = (uint32_t)(ASZ + (n0 + (lane & 7) + ((lane >> 4) * 8)) * PITCH
                               + ((lane >> 3) & 1) * 16);
    int gID = lane >> 2, tig = lane & 3;
    int gtid = (wid >> 2) * 32 + lane;   // 0..63 within m-group
    const float RS = 1.0f / 256.0f;      // undo the x16*x16 feature scaling

    int t = blockIdx.x;
    if (t >= NTILES) return;
    const uint8_t *Asrc, *Bsrc;
    int n2, pt0, pi0;
    gemm_decode(t, &Asrc, &Bsrc, &n2, &pt0, &pi0);

    gemm_load_stage(sb, 0, 0, tid, Asrc, Bsrc); CP_COMMIT();
    gemm_load_stage(sb, 1, 1, tid, Asrc, Bsrc); CP_COMMIT();

    while (true) {
        int tn = t + GRID_GEMM;
        bool more = (tn < NTILES);
        const uint8_t *An = nullptr, *Bn = nullptr;
        int nn2, npt0, npi0;
        if (more) gemm_decode(tn, &An, &Bn, &nn2, &npt0, &npi0);

        float d[2][8][4] = {};

        CP_WAIT(1); __syncthreads();
        gemm_compute_chunk(sb + aOff, sb + bOff, d);
        __syncthreads();
        if (more) { gemm_load_stage(sb, 0, 0, tid, An, Bn); CP_COMMIT(); }

        CP_WAIT(1); __syncthreads();
        gemm_compute_chunk(sb + STG + aOff, sb + STG + bOff, d);
        __syncthreads();
        if (more) { gemm_load_stage(sb, 1, 1, tid, An, Bn); CP_COMMIT(); }

        // ---- fp32 diagonal sidecar (only the 32 diagonal tiles) ----
        if (pt0 == pi0) {
            #pragma unroll
            for (int ni = 0; ni < 8; ni++) {
                int col = n0 + ni * 8 + tig * 2;
                #pragma unroll
                for (int mi = 0; mi < 2; mi++) {
                    int row = m0 + mi * 16 + gID;
                    #pragma unroll
                    for (int k = 0; k < 4; k++) {
                        int r = row + (k >> 1) * 8, c = col + (k & 1);
                        if (r == c) g_diag[(size_t)n2 * PD + pt0 + r] = d[mi][ni][k] * RS;
                    }
                }
            }
        }

        // ---- epilogue: per-m-group (named barriers, 64 thr), fp8 staging ----
        char* epi = smem + EPI_OFF;
        NAMED_BAR64(1 + mw);   // group's previous-tile epi reads complete before overwrite
        #pragma unroll
        for (int ni = 0; ni < 8; ni++) {
            float mx0 = -2.0f, mx1 = -2.0f;
            int col = n0 + ni * 8 + tig * 2;
            #pragma unroll
            for (int mi = 0; mi < 2; mi++) {
                float* dd = d[mi][ni];
                float v0 = dd[0] * RS, v1 = dd[1] * RS;
                float v2 = dd[2] * RS, v3 = dd[3] * RS;
                int row = m0 + mi * 16 + gID;
                *(uint16_t*)(epi + row * EPITCH8 + col) = pack_e4m3(v0, v1);
                *(uint16_t*)(epi + (row + 8) * EPITCH8 + col) = pack_e4m3(v2, v3);
                mx0 = fmaxf(mx0, fmaxf(v0, v2));
                mx1 = fmaxf(mx1, fmaxf(v1, v3));
            }
            #pragma unroll
            for (int o = 4; o < 32; o <<= 1) {
                mx0 = fmaxf(mx0, __shfl_xor_sync(0xffffffffu, mx0, o));
                mx1 = fmaxf(mx1, __shfl_xor_sync(0xffffffffu, mx1, o));
            }
            if (lane < 4) {
                int pi = pi0 + col;
                atomicMin((int*)&g_colmin[(size_t)n2 * PD + pi],
                          __float_as_int(0.5f - 0.5f * mx0));
                atomicMin((int*)&g_colmin[(size_t)n2 * PD + pi + 1],
                          __float_as_int(0.5f - 0.5f * mx1));
            }
        }
        NAMED_BAR64(1 + mw);   // group's epi rows fully written
        #pragma unroll
        for (int it = 0; it < 4; it++) {
            int idx = it * 64 + gtid;          // 256 = 32 rows x 8 uint4
            int r = m0 + (idx >> 3), q = idx & 7;
            uint4 v = *(uint4*)(epi + r * EPITCH8 + q * 16);
            *(uint4*)(g_dot8 + ((size_t)n2 * PD + pt0 + r) * PD + pi0 + q * 16) = v;
        }

        if (!more) break;
        t = tn; Asrc = An; Bsrc = Bn; n2 = nn2; pt0 = npt0; pi0 = npi0;
    }
}

// ---------------- kernel 4: partial column sums (no atomics in the hot loop) ----------------
// Each block sums SC_ROWS=32 rows of exp(c1*(dot-dmax)) for its 1024-column strip
// and writes UNCONTENDED partials to g_Sp[chunk][n][pi]. 1024 blocks -> high occ.
#define SC_ROWS 32
__global__ void __launch_bounds__(256) k_sumcols() {
    int n = (NS - 1) - (int)blockIdx.z;
    int chunk = blockIdx.y;
    int pi = (blockIdx.x * 256 + threadIdx.x) * 4;
    int pt0 = PD - SC_ROWS - chunk * SC_ROWS;
    float4 mn4 = *(float4*)&g_colmin[(size_t)n * PD + pi];
    float mns[4] = {mn4.x, mn4.y, mn4.z, mn4.w};
    float c2[4], bs[4], sum[4];
    #pragma unroll
    for (int j = 0; j < 4; j++) {
        c2[j] = (5.0f * LOG2E) / (mns[j] + EPSF);
        bs[j] = -c2[j] * (1.0f - 2.0f * mns[j]);   // -c2*dmax
        sum[j] = 0.0f;
    }
    const uint8_t* col = g_dot8 + ((size_t)n * PD + pt0) * PD + pi;
    #pragma unroll
    for (int r = 0; r < SC_ROWS; r++) {
        uint32_t v = *(const uint32_t*)(col + (size_t)r * PD);
        float2 f0 = __half22float2(unpack_e4m3((uint16_t)(v & 0xffff)));
        float2 f1 = __half22float2(unpack_e4m3((uint16_t)(v >> 16)));
        sum[0] += ex2(fmaf(f0.x, c2[0], bs[0]));
        sum[1] += ex2(fmaf(f0.y, c2[1], bs[1]));
        sum[2] += ex2(fmaf(f1.x, c2[2], bs[2]));
        sum[3] += ex2(fmaf(f1.y, c2[3], bs[3]));
    }
    *(float4*)&g_Sp[((size_t)chunk * NS + n) * PD + pi] = make_float4(sum[0], sum[1], sum[2], sum[3]);
}

// ---------------- kernel 4b: fold partials into g_S (parallel, 16 adders/address) ----------------
__global__ void __launch_bounds__(256) k_reduceS() {
    int idx = blockIdx.x * 256 + threadIdx.x;   // column index 0..NS*PD-1 (coalesced)
    int c0 = blockIdx.y * 8;                    // 16 chunk-groups of 8
    float s = 0.0f;
    #pragma unroll
    for (int j = 0; j < 8; j++)
        s += g_Sp[(size_t)(c0 + j) * NS * PD + idx];
    atomicAdd(&g_S[idx], s);
}

// ---------------- kernel 5: final scalar ----------------
// cx_sp is exactly the identity in fp32 (off-diagonal exponents <= -225 underflow),
// so m[pt] = 0.5 * (1 + cx_feat[pt][pt]); diagonal comes from the fp32 sidecar.
__global__ void k_final(float* __restrict__ out) {
    __shared__ float sh[256];
    __shared__ float lossn[NS];
    int tid = threadIdx.x;
    for (int n = 0; n < NS; n++) {
        float s = 0.0f;
        for (int p = tid; p < PD; p += 256) {
            float mn = g_colmin[(size_t)n * PD + p];
            float c1 = 5.0f / (mn + EPSF);
            float dmax = 1.0f - 2.0f * mn;
            float dd = g_diag[(size_t)n * PD + p];
            float cxf = fexp(c1 * (dd - dmax)) / g_S[(size_t)n * PD + p];
            s += 0.5f + 0.5f * cxf;
        }
        sh[tid] = s; __syncthreads();
        for (int o = 128; o > 0; o >>= 1) { if (tid < o) sh[tid] += sh[tid + o]; __syncthreads(); }
        if (tid == 0) lossn[n] = -logf(sh[0] * (1.0f / (float)PD));
        __syncthreads();
    }
    if (tid == 0) {
        float acc = 0.0f;
        for (int n = 0; n < NS; n++) acc += lossn[n];
        out[0] = acc * (1.0f / (float)NS);
    }
}

// ---------------- launch ----------------
extern "C" void kernel_launch(void* const* d_in, const int* in_sizes, int n_in,
                              void* d_out, int out_size) {
    const float* I = (const float*)d_in[0];
    const float* T = (const float*)d_in[1];
    float* out = (float*)d_out;

    cudaFuncSetAttribute(k_gemm, cudaFuncAttributeMaxDynamicSharedMemorySize, GEMM_SMEM_BYTES);

    k_mean<<<CD, 256>>>(T);
    k_norm2<<<dim3(PD / NP, NS, 2), 256>>>(I, T);
    k_gemm<<<GRID_GEMM, 256, GEMM_SMEM_BYTES>>>();
    k_sumcols<<<dim3(PD / 1024, SC_CHUNKS, NS), 256>>>();
    k_reduceS<<<dim3(NS * PD / 256, SC_CHUNKS / 8), 256>>>();
    k_final<<<1, 256>>>(out);
}

// round 15
// speedup vs baseline: 1.0292x; 1.0113x over previous
#include <cuda_runtime.h>
#include <cuda_fp16.h>
#include <cuda_bf16.h>
#include <cstdint>

// ---------------- problem constants ----------------
#define NS 2
#define CD 256
#define PD 4096            // 64*64
#define EPSF 1e-5f
#define LOG2E 1.4426950408889634f

// ---------------- device scratch (no runtime allocs allowed) ----------------
static __device__ uint8_t  g_dot8[(size_t)NS * PD * PD];  // 32 MiB: dot[n][pt][pi] in e4m3
static __device__ uint8_t  g_Tn[(size_t)NS * PD * CD];    // normalized T, fp8 e4m3 x16, [n][p][c]
static __device__ uint8_t  g_In[(size_t)NS * PD * CD];    // normalized I, fp8 e4m3 x16, [n][p][c]
static __device__ float g_meanT[CD];
static __device__ float g_colmin[NS * PD];   // min over pt of raw=(1-dot)/2 per (n,pi); >=0
static __device__ float g_S[NS * PD];        // sum_pt exp(c1*(dot-dmax)) per (n,pi)
static __device__ float g_diag[NS * PD];     // fp32 dot diagonal (exact numerator)

// ---------------- asm helpers (baseline sm_80/sm_89 ISA only) ----------------
__device__ __forceinline__ uint32_t smem_to_u32(const void* p) {
    uint32_t a;
    asm("{ .reg .u64 t; cvta.to.shared.u64 t, %1; cvt.u32.u64 %0, t; }" : "=r"(a) : "l"(p));
    return a;
}
#define CP_ASYNC16(dst, src) \
    asm volatile("cp.async.cg.shared.global [%0], [%1], 16;" :: "r"(dst), "l"(src) : "memory")
#define CP_COMMIT() asm volatile("cp.async.commit_group;" ::: "memory")
#define CP_WAIT(N)  asm volatile("cp.async.wait_group %0;" :: "n"(N) : "memory")
#define NAMED_BAR64(id) asm volatile("bar.sync %0, 64;" :: "r"(id) : "memory")

#define LDSM_X4(R, addr) \
    asm volatile("ldmatrix.sync.aligned.m8n8.x4.shared.b16 {%0,%1,%2,%3}, [%4];" \
        : "=r"((R)[0]), "=r"((R)[1]), "=r"((R)[2]), "=r"((R)[3]) : "r"(addr))

// fp8 e4m3 MMA: m16n8k32, A row-major (K-major), B col-major (K-major), f32 accum
#define MMA_FP8(D, A, B0, B1) \
    asm volatile("mma.sync.aligned.m16n8k32.row.col.f32.e4m3.e4m3.f32 " \
        "{%0,%1,%2,%3}, {%4,%5,%6,%7}, {%8,%9}, {%0,%1,%2,%3};" \
        : "+f"((D)[0]), "+f"((D)[1]), "+f"((D)[2]), "+f"((D)[3]) \
        : "r"((A)[0]), "r"((A)[1]), "r"((A)[2]), "r"((A)[3]), "r"(B0), "r"(B1))

// pack two floats -> e4m3x2 (lo = first elem, hi = second elem)
__device__ __forceinline__ uint16_t pack_e4m3(float lo, float hi) {
    uint16_t r;
    asm("cvt.rn.satfinite.e4m3x2.f32 %0, %1, %2;" : "=h"(r) : "f"(hi), "f"(lo));
    return r;
}
// unpack e4m3x2 (16 bits) -> half2
__device__ __forceinline__ __half2 unpack_e4m3(uint16_t v) {
    uint32_t r;
    asm("cvt.rn.f16x2.e4m3x2 %0, %1;" : "=r"(r) : "h"(v));
    return *(__half2*)&r;
}
__device__ __forceinline__ float ex2(float x) {
    float r;
    asm("ex2.approx.ftz.f32 %0, %1;" : "=f"(r) : "f"(x));
    return r;
}
__device__ __forceinline__ float fexp(float x) {
    return ex2(fmaxf(x, -120.0f) * LOG2E);
}

// ---------------- kernel 1: meanT per channel (+ fused accumulator init) ----------------
__global__ void k_mean(const float* __restrict__ T) {
    int c = blockIdx.x;       // 256
    int tid = threadIdx.x;    // 256
    if (tid < 32) {           // 256 blocks x 32 = 8192 = NS*PD
        int i = c * 32 + tid;
        g_colmin[i] = 3.402823466e38f;
        g_S[i] = 0.0f;
    }
    float s = 0.0f;
    #pragma unroll
    for (int n = 0; n < NS; n++) {
        const float4* b4 = (const float4*)(T + ((size_t)n * CD + c) * PD);
        #pragma unroll
        for (int i = tid; i < PD / 4; i += 256) {
            float4 v = b4[i];
            s += v.x + v.y + v.z + v.w;
        }
    }
    __shared__ float sh[256];
    sh[tid] = s; __syncthreads();
    for (int o = 128; o > 0; o >>= 1) { if (tid < o) sh[tid] += sh[tid + o]; __syncthreads(); }
    if (tid == 0) g_meanT[c] = sh[0] * (1.0f / (float)(NS * PD));
}

// ---------------- kernel 2: center + normalize(+x16) + transpose -> fp8 ----------------
#define NP 32
__global__ void __launch_bounds__(256) k_norm2(const float* __restrict__ I,
                                               const float* __restrict__ T) {
    const float* X = blockIdx.z ? I : T;
    uint8_t* out = blockIdx.z ? g_In : g_Tn;
    int n = blockIdx.y;
    int p0 = blockIdx.x * NP;
    int tid = threadIdx.x;
    __shared__ float buf[CD][NP + 1];   // [c][p]
    __shared__ float nrm[8][NP];
    __shared__ float scl[NP];

    const float* base = X + (size_t)n * CD * PD + p0;
    #pragma unroll
    for (int it = 0; it < 8; it++) {
        int idx = it * 256 + tid;       // 2048 = 256 c * 8 float4
        int c = idx >> 3, j = idx & 7;
        float4 v = *(const float4*)(base + (size_t)c * PD + j * 4);
        float mc = g_meanT[c];
        buf[c][j * 4 + 0] = v.x - mc;
        buf[c][j * 4 + 1] = v.y - mc;
        buf[c][j * 4 + 2] = v.z - mc;
        buf[c][j * 4 + 3] = v.w - mc;
    }
    __syncthreads();
    {
        int p = tid & 31, k = tid >> 5;   // warp k sums c-chunk k*32..k*32+31
        float s = 0.0f;
        #pragma unroll
        for (int m = 0; m < 32; m++) { float v = buf[k * 32 + m][p]; s += v * v; }
        nrm[k][p] = s;
    }
    __syncthreads();
    if (tid < NP) {
        float t = 0.0f;
        #pragma unroll
        for (int k = 0; k < 8; k++) t += nrm[k][tid];
        scl[tid] = rsqrtf(t) * 16.0f;   // x16 scale: e4m3 values ~O(1)
    }
    __syncthreads();
    uint8_t* ob = out + ((size_t)n * PD + p0) * CD;
    #pragma unroll
    for (int it = 0; it < 4; it++) {
        int idx = it * 256 + tid;       // 1024 = 32 p * 32 8-byte groups
        int p = idx >> 5, q = idx & 31;
        float sc = scl[p];
        uint16_t h[4];
        #pragma unroll
        for (int i = 0; i < 4; i++) {
            float a = buf[q * 8 + 2 * i + 0][p] * sc;
            float b = buf[q * 8 + 2 * i + 1][p] * sc;
            h[i] = pack_e4m3(a, b);
        }
        uint2 u;
        u.x = (uint32_t)h[0] | ((uint32_t)h[1] << 16);
        u.y = (uint32_t)h[2] | ((uint32_t)h[3] << 16);
        *(uint2*)(ob + (size_t)p * CD + q * 8) = u;
    }
}

// ---------------- kernel 3: persistent fp8 MMA GEMM, 128x128 tiles, 2 CTAs/SM ----------------
#define BM 128
#define BN 128
#define PITCH 144                 // 128 fp8 bytes + 16B pad
#define ASZ (BM * PITCH)          // 18432
#define BSZ (BN * PITCH)          // 18432
#define STG (ASZ + BSZ)           // 36864
#define EPI_OFF (2 * STG)         // 73728
#define EPITCH8 144               // epilogue fp8 row pitch (128 + 16)
#define GEMM_SMEM_BYTES (EPI_OFF + BM * EPITCH8)  // 73728 + 18432 = 92160
#define GRID_GEMM 296             // 2 CTAs per SM
#define NTILES (NS * (PD / BM) * (PD / BN))       // 2048

__device__ __forceinline__ void gemm_load_stage(
    uint32_t sb, int stage, int kc, int tid,
    const uint8_t* Asrc, const uint8_t* Bsrc) {
    uint32_t base = sb + stage * STG;
    #pragma unroll
    for (int i = 0; i < 4; i++) {               // A: 128 rows x 8 chunks = 1024
        int id = tid + i * 256;
        int row = id >> 3, g = id & 7;
        CP_ASYNC16(base + row * PITCH + g * 16, Asrc + (size_t)row * CD + kc * 128 + g * 16);
    }
    #pragma unroll
    for (int i = 0; i < 4; i++) {               // B: 128 rows x 8 chunks = 1024
        int id = tid + i * 256;
        int row = id >> 3, g = id & 7;
        CP_ASYNC16(base + ASZ + row * PITCH + g * 16, Bsrc + (size_t)row * CD + kc * 128 + g * 16);
    }
}

__device__ __forceinline__ void gemm_compute_chunk(uint32_t aB, uint32_t bB, float d[2][8][4]) {
    #pragma unroll
    for (int kk = 0; kk < 4; kk++) {   // 4 x k32 (32 bytes each)
        uint32_t a[2][4], b[4][4];
        LDSM_X4(a[0], aB + kk * 32);
        LDSM_X4(a[1], aB + 16 * PITCH + kk * 32);
        #pragma unroll
        for (int nb = 0; nb < 4; nb++)
            LDSM_X4(b[nb], bB + nb * 16 * PITCH + kk * 32);
        #pragma unroll
        for (int mi = 0; mi < 2; mi++)
            #pragma unroll
            for (int ni = 0; ni < 8; ni++) {
                uint32_t* bp = b[ni >> 1];
                MMA_FP8(d[mi][ni], a[mi], bp[(ni & 1) * 2], bp[(ni & 1) * 2 + 1]);
            }
    }
}

__device__ __forceinline__ void gemm_decode(int t, const uint8_t** A, const uint8_t** B,
                                            int* n2, int* pt0, int* pi0) {
    *n2 = t >> 10;                // 1024 tiles per sample
    int rem = t & 1023;
    *pt0 = (rem >> 5) * BM;       // 32 pt tiles
    *pi0 = (rem & 31) * BN;       // 32 pi tiles
    *A = g_Tn + ((size_t)(*n2) * PD + *pt0) * CD;
    *B = g_In + ((size_t)(*n2) * PD + *pi0) * CD;
}

__global__ void __launch_bounds__(256, 2) k_gemm() {
    extern __shared__ char smem[];
    uint32_t sb = smem_to_u32(smem);
    int tid = threadIdx.x, lane = tid & 31, wid = tid >> 5;

    int mw = wid & 3;               // m-group: 2 warps (wid&3 equal) own rows m0..m0+31
    int m0 = mw * 32;
    int n0 = (wid >> 2) * 64;       // 2 N-warps x 64 cols
    uint32_t aOff = (uint32_t)((m0 + (lane & 15)) * PITCH + (lane >> 4) * 16);
    uint32_t bOff = (uint32_t)(ASZ + (n0 + (lane & 7) + ((lane >> 4) * 8)) * PITCH
                               + ((lane >> 3) & 1) * 16);
    int gID = lane >> 2, tig = lane & 3;
    int gtid = (wid >> 2) * 32 + lane;   // 0..63 within m-group
    const float RS = 1.0f / 256.0f;      // undo the x16*x16 feature scaling

    int t = blockIdx.x;
    if (t >= NTILES) return;
    const uint8_t *Asrc, *Bsrc;
    int n2, pt0, pi0;
    gemm_decode(t, &Asrc, &Bsrc, &n2, &pt0, &pi0);

    gemm_load_stage(sb, 0, 0, tid, Asrc, Bsrc); CP_COMMIT();
    gemm_load_stage(sb, 1, 1, tid, Asrc, Bsrc); CP_COMMIT();

    while (true) {
        int tn = t + GRID_GEMM;
        bool more = (tn < NTILES);
        const uint8_t *An = nullptr, *Bn = nullptr;
        int nn2, npt0, npi0;
        if (more) gemm_decode(tn, &An, &Bn, &nn2, &npt0, &npi0);

        float d[2][8][4] = {};

        CP_WAIT(1); __syncthreads();
        gemm_compute_chunk(sb + aOff, sb + bOff, d);
        __syncthreads();
        if (more) { gemm_load_stage(sb, 0, 0, tid, An, Bn); CP_COMMIT(); }

        CP_WAIT(1); __syncthreads();
        gemm_compute_chunk(sb + STG + aOff, sb + STG + bOff, d);
        __syncthreads();
        if (more) { gemm_load_stage(sb, 1, 1, tid, An, Bn); CP_COMMIT(); }

        // ---- fp32 diagonal sidecar (only the 32 diagonal tiles) ----
        if (pt0 == pi0) {
            #pragma unroll
            for (int ni = 0; ni < 8; ni++) {
                int col = n0 + ni * 8 + tig * 2;
                #pragma unroll
                for (int mi = 0; mi < 2; mi++) {
                    int row = m0 + mi * 16 + gID;
                    #pragma unroll
                    for (int k = 0; k < 4; k++) {
                        int r = row + (k >> 1) * 8, c = col + (k & 1);
                        if (r == c) g_diag[(size_t)n2 * PD + pt0 + r] = d[mi][ni][k] * RS;
                    }
                }
            }
        }

        // ---- epilogue: per-m-group (named barriers, 64 thr), fp8 staging ----
        char* epi = smem + EPI_OFF;
        NAMED_BAR64(1 + mw);   // group's previous-tile epi reads complete before overwrite
        #pragma unroll
        for (int ni = 0; ni < 8; ni++) {
            float mx0 = -2.0f, mx1 = -2.0f;
            int col = n0 + ni * 8 + tig * 2;
            #pragma unroll
            for (int mi = 0; mi < 2; mi++) {
                float* dd = d[mi][ni];
                float v0 = dd[0] * RS, v1 = dd[1] * RS;
                float v2 = dd[2] * RS, v3 = dd[3] * RS;
                int row = m0 + mi * 16 + gID;
                *(uint16_t*)(epi + row * EPITCH8 + col) = pack_e4m3(v0, v1);
                *(uint16_t*)(epi + (row + 8) * EPITCH8 + col) = pack_e4m3(v2, v3);
                mx0 = fmaxf(mx0, fmaxf(v0, v2));
                mx1 = fmaxf(mx1, fmaxf(v1, v3));
            }
            #pragma unroll
            for (int o = 4; o < 32; o <<= 1) {
                mx0 = fmaxf(mx0, __shfl_xor_sync(0xffffffffu, mx0, o));
                mx1 = fmaxf(mx1, __shfl_xor_sync(0xffffffffu, mx1, o));
            }
            if (lane < 4) {
                int pi = pi0 + col;
                atomicMin((int*)&g_colmin[(size_t)n2 * PD + pi],
                          __float_as_int(0.5f - 0.5f * mx0));
                atomicMin((int*)&g_colmin[(size_t)n2 * PD + pi + 1],
                          __float_as_int(0.5f - 0.5f * mx1));
            }
        }
        NAMED_BAR64(1 + mw);   // group's epi rows fully written
        #pragma unroll
        for (int it = 0; it < 4; it++) {
            int idx = it * 64 + gtid;          // 256 = 32 rows x 8 uint4
            int r = m0 + (idx >> 3), q = idx & 7;
            uint4 v = *(uint4*)(epi + r * EPITCH8 + q * 16);
            *(uint4*)(g_dot8 + ((size_t)n2 * PD + pt0 + r) * PD + pi0 + q * 16) = v;
        }

        if (!more) break;
        t = tn; Asrc = An; Bsrc = Bn; n2 = nn2; pt0 = npt0; pi0 = npi0;
    }
}

// ---------------- kernel 4: column sums S[n][pi] = sum_pt exp(c1*(dot-dmax)) ----------------
// Verified-best shape (R12): 4 cols/thread via uint32 loads, 64 rows/block ->
// 64 atomic adders per g_S address, grid (4, 64, 2) = 512 blocks, unroll 16.
// Reverse traversal (sample 1 / high pt first) catches the GEMM's freshest L2 lines.
#define SC_ROWS 64
__global__ void __launch_bounds__(256) k_sumcols() {
    int n = (NS - 1) - (int)blockIdx.z;
    int pi = (blockIdx.x * 256 + threadIdx.x) * 4;
    int pt0 = PD - SC_ROWS - (int)blockIdx.y * SC_ROWS;
    float4 mn4 = *(float4*)&g_colmin[(size_t)n * PD + pi];
    float mns[4] = {mn4.x, mn4.y, mn4.z, mn4.w};
    float c2[4], bs[4], sum[4];
    #pragma unroll
    for (int j = 0; j < 4; j++) {
        c2[j] = (5.0f * LOG2E) / (mns[j] + EPSF);
        bs[j] = -c2[j] * (1.0f - 2.0f * mns[j]);   // -c2*dmax
        sum[j] = 0.0f;
    }
    const uint8_t* col = g_dot8 + ((size_t)n * PD + pt0) * PD + pi;
    #pragma unroll 16
    for (int r = 0; r < SC_ROWS; r++) {
        uint32_t v = *(const uint32_t*)(col + (size_t)r * PD);
        float2 f0 = __half22float2(unpack_e4m3((uint16_t)(v & 0xffff)));
        float2 f1 = __half22float2(unpack_e4m3((uint16_t)(v >> 16)));
        sum[0] += ex2(fmaf(f0.x, c2[0], bs[0]));
        sum[1] += ex2(fmaf(f0.y, c2[1], bs[1]));
        sum[2] += ex2(fmaf(f1.x, c2[2], bs[2]));
        sum[3] += ex2(fmaf(f1.y, c2[3], bs[3]));
    }
    #pragma unroll
    for (int j = 0; j < 4; j++)
        atomicAdd(&g_S[(size_t)n * PD + pi + j], sum[j]);
}

// ---------------- kernel 5: final scalar ----------------
// cx_sp is exactly the identity in fp32 (off-diagonal exponents <= -225 underflow),
// so m[pt] = 0.5 * (1 + cx_feat[pt][pt]); diagonal comes from the fp32 sidecar.
__global__ void k_final(float* __restrict__ out) {
    __shared__ float sh[256];
    __shared__ float lossn[NS];
    int tid = threadIdx.x;
    for (int n = 0; n < NS; n++) {
        float s = 0.0f;
        for (int p = tid; p < PD; p += 256) {
            float mn = g_colmin[(size_t)n * PD + p];
            float c1 = 5.0f / (mn + EPSF);
            float dmax = 1.0f - 2.0f * mn;
            float dd = g_diag[(size_t)n * PD + p];
            float cxf = fexp(c1 * (dd - dmax)) / g_S[(size_t)n * PD + p];
            s += 0.5f + 0.5f * cxf;
        }
        sh[tid] = s; __syncthreads();
        for (int o = 128; o > 0; o >>= 1) { if (tid < o) sh[tid] += sh[tid + o]; __syncthreads(); }
        if (tid == 0) lossn[n] = -logf(sh[0] * (1.0f / (float)PD));
        __syncthreads();
    }
    if (tid == 0) {
        float acc = 0.0f;
        for (int n = 0; n < NS; n++) acc += lossn[n];
        out[0] = acc * (1.0f / (float)NS);
    }
}

// ---------------- launch ----------------
extern "C" void kernel_launch(void* const* d_in, const int* in_sizes, int n_in,
                              void* d_out, int out_size) {
    const float* I = (const float*)d_in[0];
    const float* T = (const float*)d_in[1];
    float* out = (float*)d_out;

    cudaFuncSetAttribute(k_gemm, cudaFuncAttributeMaxDynamicSharedMemorySize, GEMM_SMEM_BYTES);

    k_mean<<<CD, 256>>>(T);
    k_norm2<<<dim3(PD / NP, NS, 2), 256>>>(I, T);
    k_gemm<<<GRID_GEMM, 256, GEMM_SMEM_BYTES>>>();
    k_sumcols<<<dim3(PD / 1024, PD / SC_ROWS, NS), 256>>>();
    k_final<<<1, 256>>>(out);
}

// round 16
// speedup vs baseline: 1.0409x; 1.0114x over previous
#include <cuda_runtime.h>
#include <cuda_fp16.h>
#include <cuda_bf16.h>
#include <cstdint>

// ---------------- problem constants ----------------
#define NS 2
#define CD 256
#define PD 4096            // 64*64
#define EPSF 1e-5f
#define LOG2E 1.4426950408889634f

// ---------------- device scratch (no runtime allocs allowed) ----------------
static __device__ uint8_t  g_dot8[(size_t)NS * PD * PD];  // 32 MiB: dot[n][pt][pi] in e4m3
static __device__ uint8_t  g_Tn[(size_t)NS * PD * CD];    // normalized T, fp8 e4m3 x16, [n][p][c]
static __device__ uint8_t  g_In[(size_t)NS * PD * CD];    // normalized I, fp8 e4m3 x16, [n][p][c]
static __device__ float g_meanT[CD];
static __device__ float g_colmin[NS * PD];   // min over pt of raw=(1-dot)/2 per (n,pi); >=0
#define NREP 4
static __device__ float g_Sr[NREP][NS * PD]; // replica column-sum accumulators (32 adders each)
static __device__ float g_diag[NS * PD];     // fp32 dot diagonal (exact numerator)

// ---------------- asm helpers (baseline sm_80/sm_89 ISA only) ----------------
__device__ __forceinline__ uint32_t smem_to_u32(const void* p) {
    uint32_t a;
    asm("{ .reg .u64 t; cvta.to.shared.u64 t, %1; cvt.u32.u64 %0, t; }" : "=r"(a) : "l"(p));
    return a;
}
#define CP_ASYNC16(dst, src) \
    asm volatile("cp.async.cg.shared.global [%0], [%1], 16;" :: "r"(dst), "l"(src) : "memory")
#define CP_COMMIT() asm volatile("cp.async.commit_group;" ::: "memory")
#define CP_WAIT(N)  asm volatile("cp.async.wait_group %0;" :: "n"(N) : "memory")
#define NAMED_BAR64(id) asm volatile("bar.sync %0, 64;" :: "r"(id) : "memory")

#define LDSM_X4(R, addr) \
    asm volatile("ldmatrix.sync.aligned.m8n8.x4.shared.b16 {%0,%1,%2,%3}, [%4];" \
        : "=r"((R)[0]), "=r"((R)[1]), "=r"((R)[2]), "=r"((R)[3]) : "r"(addr))

// fp8 e4m3 MMA: m16n8k32, A row-major (K-major), B col-major (K-major), f32 accum
#define MMA_FP8(D, A, B0, B1) \
    asm volatile("mma.sync.aligned.m16n8k32.row.col.f32.e4m3.e4m3.f32 " \
        "{%0,%1,%2,%3}, {%4,%5,%6,%7}, {%8,%9}, {%0,%1,%2,%3};" \
        : "+f"((D)[0]), "+f"((D)[1]), "+f"((D)[2]), "+f"((D)[3]) \
        : "r"((A)[0]), "r"((A)[1]), "r"((A)[2]), "r"((A)[3]), "r"(B0), "r"(B1))

// pack two floats -> e4m3x2 (lo = first elem, hi = second elem)
__device__ __forceinline__ uint16_t pack_e4m3(float lo, float hi) {
    uint16_t r;
    asm("cvt.rn.satfinite.e4m3x2.f32 %0, %1, %2;" : "=h"(r) : "f"(hi), "f"(lo));
    return r;
}
// unpack e4m3x2 (16 bits) -> half2
__device__ __forceinline__ __half2 unpack_e4m3(uint16_t v) {
    uint32_t r;
    asm("cvt.rn.f16x2.e4m3x2 %0, %1;" : "=r"(r) : "h"(v));
    return *(__half2*)&r;
}
__device__ __forceinline__ float ex2(float x) {
    float r;
    asm("ex2.approx.ftz.f32 %0, %1;" : "=f"(r) : "f"(x));
    return r;
}
__device__ __forceinline__ float fexp(float x) {
    return ex2(fmaxf(x, -120.0f) * LOG2E);
}

// ---------------- kernel 1: meanT per channel (+ fused accumulator init) ----------------
__global__ void k_mean(const float* __restrict__ T) {
    int c = blockIdx.x;       // 256
    int tid = threadIdx.x;    // 256
    if (tid < 32) {           // 256 blocks x 32 = 8192 = NS*PD
        g_colmin[c * 32 + tid] = 3.402823466e38f;
    }
    if (tid < 128) {          // 256 blocks x 128 = 32768 = NREP*NS*PD
        int i = c * 128 + tid;
        (&g_Sr[0][0])[i] = 0.0f;
    }
    float s = 0.0f;
    #pragma unroll
    for (int n = 0; n < NS; n++) {
        const float4* b4 = (const float4*)(T + ((size_t)n * CD + c) * PD);
        #pragma unroll
        for (int i = tid; i < PD / 4; i += 256) {
            float4 v = b4[i];
            s += v.x + v.y + v.z + v.w;
        }
    }
    __shared__ float sh[256];
    sh[tid] = s; __syncthreads();
    for (int o = 128; o > 0; o >>= 1) { if (tid < o) sh[tid] += sh[tid + o]; __syncthreads(); }
    if (tid == 0) g_meanT[c] = sh[0] * (1.0f / (float)(NS * PD));
}

// ---------------- kernel 2: center + normalize(+x16) + transpose -> fp8 ----------------
#define NP 32
__global__ void __launch_bounds__(256) k_norm2(const float* __restrict__ I,
                                               const float* __restrict__ T) {
    const float* X = blockIdx.z ? I : T;
    uint8_t* out = blockIdx.z ? g_In : g_Tn;
    int n = blockIdx.y;
    int p0 = blockIdx.x * NP;
    int tid = threadIdx.x;
    __shared__ float buf[CD][NP + 1];   // [c][p]
    __shared__ float nrm[8][NP];
    __shared__ float scl[NP];

    const float* base = X + (size_t)n * CD * PD + p0;
    #pragma unroll
    for (int it = 0; it < 8; it++) {
        int idx = it * 256 + tid;       // 2048 = 256 c * 8 float4
        int c = idx >> 3, j = idx & 7;
        float4 v = *(const float4*)(base + (size_t)c * PD + j * 4);
        float mc = g_meanT[c];
        buf[c][j * 4 + 0] = v.x - mc;
        buf[c][j * 4 + 1] = v.y - mc;
        buf[c][j * 4 + 2] = v.z - mc;
        buf[c][j * 4 + 3] = v.w - mc;
    }
    __syncthreads();
    {
        int p = tid & 31, k = tid >> 5;   // warp k sums c-chunk k*32..k*32+31
        float s = 0.0f;
        #pragma unroll
        for (int m = 0; m < 32; m++) { float v = buf[k * 32 + m][p]; s += v * v; }
        nrm[k][p] = s;
    }
    __syncthreads();
    if (tid < NP) {
        float t = 0.0f;
        #pragma unroll
        for (int k = 0; k < 8; k++) t += nrm[k][tid];
        scl[tid] = rsqrtf(t) * 16.0f;   // x16 scale: e4m3 values ~O(1)
    }
    __syncthreads();
    uint8_t* ob = out + ((size_t)n * PD + p0) * CD;
    #pragma unroll
    for (int it = 0; it < 4; it++) {
        int idx = it * 256 + tid;       // 1024 = 32 p * 32 8-byte groups
        int p = idx >> 5, q = idx & 31;
        float sc = scl[p];
        uint16_t h[4];
        #pragma unroll
        for (int i = 0; i < 4; i++) {
            float a = buf[q * 8 + 2 * i + 0][p] * sc;
            float b = buf[q * 8 + 2 * i + 1][p] * sc;
            h[i] = pack_e4m3(a, b);
        }
        uint2 u;
        u.x = (uint32_t)h[0] | ((uint32_t)h[1] << 16);
        u.y = (uint32_t)h[2] | ((uint32_t)h[3] << 16);
        *(uint2*)(ob + (size_t)p * CD + q * 8) = u;
    }
}

// ---------------- kernel 3: persistent fp8 MMA GEMM, 128x128 tiles, 2 CTAs/SM ----------------
#define BM 128
#define BN 128
#define PITCH 144                 // 128 fp8 bytes + 16B pad
#define ASZ (BM * PITCH)          // 18432
#define BSZ (BN * PITCH)          // 18432
#define STG (ASZ + BSZ)           // 36864
#define EPI_OFF (2 * STG)         // 73728
#define EPITCH8 144               // epilogue fp8 row pitch (128 + 16)
#define GEMM_SMEM_BYTES (EPI_OFF + BM * EPITCH8)  // 73728 + 18432 = 92160
#define GRID_GEMM 296             // 2 CTAs per SM
#define NTILES (NS * (PD / BM) * (PD / BN))       // 2048

__device__ __forceinline__ void gemm_load_stage(
    uint32_t sb, int stage, int kc, int tid,
    const uint8_t* Asrc, const uint8_t* Bsrc) {
    uint32_t base = sb + stage * STG;
    #pragma unroll
    for (int i = 0; i < 4; i++) {               // A: 128 rows x 8 chunks = 1024
        int id = tid + i * 256;
        int row = id >> 3, g = id & 7;
        CP_ASYNC16(base + row * PITCH + g * 16, Asrc + (size_t)row * CD + kc * 128 + g * 16);
    }
    #pragma unroll
    for (int i = 0; i < 4; i++) {               // B: 128 rows x 8 chunks = 1024
        int id = tid + i * 256;
        int row = id >> 3, g = id & 7;
        CP_ASYNC16(base + ASZ + row * PITCH + g * 16, Bsrc + (size_t)row * CD + kc * 128 + g * 16);
    }
}

__device__ __forceinline__ void gemm_compute_chunk(uint32_t aB, uint32_t bB, float d[2][8][4]) {
    #pragma unroll
    for (int kk = 0; kk < 4; kk++) {   // 4 x k32 (32 bytes each)
        uint32_t a[2][4], b[4][4];
        LDSM_X4(a[0], aB + kk * 32);
        LDSM_X4(a[1], aB + 16 * PITCH + kk * 32);
        #pragma unroll
        for (int nb = 0; nb < 4; nb++)
            LDSM_X4(b[nb], bB + nb * 16 * PITCH + kk * 32);
        #pragma unroll
        for (int mi = 0; mi < 2; mi++)
            #pragma unroll
            for (int ni = 0; ni < 8; ni++) {
                uint32_t* bp = b[ni >> 1];
                MMA_FP8(d[mi][ni], a[mi], bp[(ni & 1) * 2], bp[(ni & 1) * 2 + 1]);
            }
    }
}

__device__ __forceinline__ void gemm_decode(int t, const uint8_t** A, const uint8_t** B,
                                            int* n2, int* pt0, int* pi0) {
    *n2 = t >> 10;                // 1024 tiles per sample
    int rem = t & 1023;
    *pt0 = (rem >> 5) * BM;       // 32 pt tiles
    *pi0 = (rem & 31) * BN;       // 32 pi tiles
    *A = g_Tn + ((size_t)(*n2) * PD + *pt0) * CD;
    *B = g_In + ((size_t)(*n2) * PD + *pi0) * CD;
}

__global__ void __launch_bounds__(256, 2) k_gemm() {
    extern __shared__ char smem[];
    uint32_t sb = smem_to_u32(smem);
    int tid = threadIdx.x, lane = tid & 31, wid = tid >> 5;

    int mw = wid & 3;               // m-group: 2 warps (wid&3 equal) own rows m0..m0+31
    int m0 = mw * 32;
    int n0 = (wid >> 2) * 64;       // 2 N-warps x 64 cols
    uint32_t aOff = (uint32_t)((m0 + (lane & 15)) * PITCH + (lane >> 4) * 16);
    uint32_t bOff = (uint32_t)(ASZ + (n0 + (lane & 7) + ((lane >> 4) * 8)) * PITCH
                               + ((lane >> 3) & 1) * 16);
    int gID = lane >> 2, tig = lane & 3;
    int gtid = (wid >> 2) * 32 + lane;   // 0..63 within m-group
    const float RS = 1.0f / 256.0f;      // undo the x16*x16 feature scaling

    int t = blockIdx.x;
    if (t >= NTILES) return;
    const uint8_t *Asrc, *Bsrc;
    int n2, pt0, pi0;
    gemm_decode(t, &Asrc, &Bsrc, &n2, &pt0, &pi0);

    gemm_load_stage(sb, 0, 0, tid, Asrc, Bsrc); CP_COMMIT();
    gemm_load_stage(sb, 1, 1, tid, Asrc, Bsrc); CP_COMMIT();

    while (true) {
        int tn = t + GRID_GEMM;
        bool more = (tn < NTILES);
        const uint8_t *An = nullptr, *Bn = nullptr;
        int nn2, npt0, npi0;
        if (more) gemm_decode(tn, &An, &Bn, &nn2, &npt0, &npi0);

        float d[2][8][4] = {};

        CP_WAIT(1); __syncthreads();
        gemm_compute_chunk(sb + aOff, sb + bOff, d);
        __syncthreads();
        if (more) { gemm_load_stage(sb, 0, 0, tid, An, Bn); CP_COMMIT(); }

        CP_WAIT(1); __syncthreads();
        gemm_compute_chunk(sb + STG + aOff, sb + STG + bOff, d);
        __syncthreads();
        if (more) { gemm_load_stage(sb, 1, 1, tid, An, Bn); CP_COMMIT(); }

        // ---- fp32 diagonal sidecar (only the 32 diagonal tiles) ----
        if (pt0 == pi0) {
            #pragma unroll
            for (int ni = 0; ni < 8; ni++) {
                int col = n0 + ni * 8 + tig * 2;
                #pragma unroll
                for (int mi = 0; mi < 2; mi++) {
                    int row = m0 + mi * 16 + gID;
                    #pragma unroll
                    for (int k = 0; k < 4; k++) {
                        int r = row + (k >> 1) * 8, c = col + (k & 1);
                        if (r == c) g_diag[(size_t)n2 * PD + pt0 + r] = d[mi][ni][k] * RS;
                    }
                }
            }
        }

        // ---- epilogue: per-m-group (named barriers, 64 thr), fp8 staging ----
        char* epi = smem + EPI_OFF;
        NAMED_BAR64(1 + mw);   // group's previous-tile epi reads complete before overwrite
        #pragma unroll
        for (int ni = 0; ni < 8; ni++) {
            float mx0 = -2.0f, mx1 = -2.0f;
            int col = n0 + ni * 8 + tig * 2;
            #pragma unroll
            for (int mi = 0; mi < 2; mi++) {
                float* dd = d[mi][ni];
                float v0 = dd[0] * RS, v1 = dd[1] * RS;
                float v2 = dd[2] * RS, v3 = dd[3] * RS;
                int row = m0 + mi * 16 + gID;
                *(uint16_t*)(epi + row * EPITCH8 + col) = pack_e4m3(v0, v1);
                *(uint16_t*)(epi + (row + 8) * EPITCH8 + col) = pack_e4m3(v2, v3);
                mx0 = fmaxf(mx0, fmaxf(v0, v2));
                mx1 = fmaxf(mx1, fmaxf(v1, v3));
            }
            #pragma unroll
            for (int o = 4; o < 32; o <<= 1) {
                mx0 = fmaxf(mx0, __shfl_xor_sync(0xffffffffu, mx0, o));
                mx1 = fmaxf(mx1, __shfl_xor_sync(0xffffffffu, mx1, o));
            }
            if (lane < 4) {
                int pi = pi0 + col;
                atomicMin((int*)&g_colmin[(size_t)n2 * PD + pi],
                          __float_as_int(0.5f - 0.5f * mx0));
                atomicMin((int*)&g_colmin[(size_t)n2 * PD + pi + 1],
                          __float_as_int(0.5f - 0.5f * mx1));
            }
        }
        NAMED_BAR64(1 + mw);   // group's epi rows fully written
        #pragma unroll
        for (int it = 0; it < 4; it++) {
            int idx = it * 64 + gtid;          // 256 = 32 rows x 8 uint4
            int r = m0 + (idx >> 3), q = idx & 7;
            uint4 v = *(uint4*)(epi + r * EPITCH8 + q * 16);
            *(uint4*)(g_dot8 + ((size_t)n2 * PD + pt0 + r) * PD + pi0 + q * 16) = v;
        }

        if (!more) break;
        t = tn; Asrc = An; Bsrc = Bn; n2 = nn2; pt0 = npt0; pi0 = npi0;
    }
}

// ---------------- kernel 4: column sums with replica-split accumulators ----------------
// 1024 blocks (R13-proven occupancy), SC_ROWS=32; each block atomicAdds into one of
// NREP=4 replica arrays -> 32 adders per address per replica (below the benign 64
// level). No fold kernel: k_final sums the 4 replicas (128 KB, free).
#define SC_ROWS 32
__global__ void __launch_bounds__(256) k_sumcols() {
    int n = (NS - 1) - (int)blockIdx.z;
    int rep = blockIdx.y & (NREP - 1);
    int pi = (blockIdx.x * 256 + threadIdx.x) * 4;
    int pt0 = PD - SC_ROWS - (int)blockIdx.y * SC_ROWS;
    float4 mn4 = *(float4*)&g_colmin[(size_t)n * PD + pi];
    float mns[4] = {mn4.x, mn4.y, mn4.z, mn4.w};
    float c2[4], bs[4], sum[4];
    #pragma unroll
    for (int j = 0; j < 4; j++) {
        c2[j] = (5.0f * LOG2E) / (mns[j] + EPSF);
        bs[j] = -c2[j] * (1.0f - 2.0f * mns[j]);   // -c2*dmax
        sum[j] = 0.0f;
    }
    const uint8_t* col = g_dot8 + ((size_t)n * PD + pt0) * PD + pi;
    #pragma unroll
    for (int r = 0; r < SC_ROWS; r++) {
        uint32_t v = *(const uint32_t*)(col + (size_t)r * PD);
        float2 f0 = __half22float2(unpack_e4m3((uint16_t)(v & 0xffff)));
        float2 f1 = __half22float2(unpack_e4m3((uint16_t)(v >> 16)));
        sum[0] += ex2(fmaf(f0.x, c2[0], bs[0]));
        sum[1] += ex2(fmaf(f0.y, c2[1], bs[1]));
        sum[2] += ex2(fmaf(f1.x, c2[2], bs[2]));
        sum[3] += ex2(fmaf(f1.y, c2[3], bs[3]));
    }
    #pragma unroll
    for (int j = 0; j < 4; j++)
        atomicAdd(&g_Sr[rep][(size_t)n * PD + pi + j], sum[j]);
}

// ---------------- kernel 5: final scalar ----------------
// cx_sp is exactly the identity in fp32 (off-diagonal exponents <= -225 underflow),
// so m[pt] = 0.5 * (1 + cx_feat[pt][pt]); diagonal comes from the fp32 sidecar.
__global__ void k_final(float* __restrict__ out) {
    __shared__ float sh[256];
    __shared__ float lossn[NS];
    int tid = threadIdx.x;
    for (int n = 0; n < NS; n++) {
        float s = 0.0f;
        for (int p = tid; p < PD; p += 256) {
            float mn = g_colmin[(size_t)n * PD + p];
            float c1 = 5.0f / (mn + EPSF);
            float dmax = 1.0f - 2.0f * mn;
            float dd = g_diag[(size_t)n * PD + p];
            float S = 0.0f;
            #pragma unroll
            for (int r = 0; r < NREP; r++) S += g_Sr[r][(size_t)n * PD + p];
            float cxf = fexp(c1 * (dd - dmax)) / S;
            s += 0.5f + 0.5f * cxf;
        }
        sh[tid] = s; __syncthreads();
        for (int o = 128; o > 0; o >>= 1) { if (tid < o) sh[tid] += sh[tid + o]; __syncthreads(); }
        if (tid == 0) lossn[n] = -logf(sh[0] * (1.0f / (float)PD));
        __syncthreads();
    }
    if (tid == 0) {
        float acc = 0.0f;
        for (int n = 0; n < NS; n++) acc += lossn[n];
        out[0] = acc * (1.0f / (float)NS);
    }
}

// ---------------- launch ----------------
extern "C" void kernel_launch(void* const* d_in, const int* in_sizes, int n_in,
                              void* d_out, int out_size) {
    const float* I = (const float*)d_in[0];
    const float* T = (const float*)d_in[1];
    float* out = (float*)d_out;

    cudaFuncSetAttribute(k_gemm, cudaFuncAttributeMaxDynamicSharedMemorySize, GEMM_SMEM_BYTES);

    k_mean<<<CD, 256>>>(T);
    k_norm2<<<dim3(PD / NP, NS, 2), 256>>>(I, T);
    k_gemm<<<GRID_GEMM, 256, GEMM_SMEM_BYTES>>>();
    k_sumcols<<<dim3(PD / 1024, PD / SC_ROWS, NS), 256>>>();
    k_final<<<1, 256>>>(out);
}